// round 1
// baseline (speedup 1.0000x reference)
#include <cuda_runtime.h>
#include <math.h>

#define BN 4
#define CW 32
#define RR 64
#define SP (RR*RR*RR)        // 262144
#define MD 8
#define M2 16
#define NLY 4
#define FCHN 128
#define PI2_64 0.09817477042468103f   // 2*pi/64

// ---------------- scratch (static device memory; no allocation) ----------------
__device__ float  g_x0[BN*CW*SP];               // 134 MB
__device__ float  g_x1[BN*CW*SP];               // 134 MB
__device__ float2 g_a [BN*CW*RR*RR*MD];         // 33.5 MB  (fwd-z out / inv-y out)
__device__ float2 g_b [BN*CW*RR*M2*MD];         // 8.4 MB   (fwd-y out / inv-x out)
__device__ float2 g_ft[BN*CW*M2*M2*MD];         // 2 MB
__device__ float2 g_sf[BN*CW*M2*M2*MD];         // 2 MB

__device__ __forceinline__ float gelu_tanh(float a) {
    float t3 = a*a*a;
    return 0.5f*a*(1.0f + tanhf(0.7978845608028654f*(a + 0.044715f*t3)));
}

// ---------------- fc0: (B,3,S) x (3,32) + b -> g_x0 ----------------
__global__ void k_fc0(const float* __restrict__ u, const float* __restrict__ w,
                      const float* __restrict__ bias) {
    __shared__ float sw[3*CW], sb[CW];
    int tid = threadIdx.x;
    if (tid < 3*CW) sw[tid] = w[tid];
    if (tid < CW)   sb[tid] = bias[tid];
    __syncthreads();
    int idx = blockIdx.x*blockDim.x + tid;
    if (idx >= BN*SP) return;
    int b = idx >> 18, s = idx & (SP-1);
    float u0 = u[(b*3+0)*SP+s], u1 = u[(b*3+1)*SP+s], u2 = u[(b*3+2)*SP+s];
#pragma unroll
    for (int o = 0; o < CW; o++) {
        g_x0[(b*CW+o)*SP + s] = sb[o] + u0*sw[o] + u1*sw[CW+o] + u2*sw[2*CW+o];
    }
}

// ---------------- forward z: real 64 -> 8 complex modes ----------------
__global__ void k_fz(int flip) {
    __shared__ float  sx[16][65];
    __shared__ float2 tw[64][MD];
    const float* __restrict__ x = flip ? g_x1 : g_x0;
    int tid = threadIdx.x;  // 128
    for (int i = tid; i < 64*MD; i += 128) {
        int w = i >> 3, k = i & 7;
        float s, c; sincosf(((w*k)&63)*PI2_64, &s, &c);
        tw[w][k] = make_float2(c, -s);
    }
    int row0 = blockIdx.x * 16;   // rows over B*C*64*64 = 524288
    for (int i = tid; i < 16*64; i += 128)
        sx[i>>6][i&63] = x[row0*64 + i];
    __syncthreads();
    int r = tid >> 3, k = tid & 7;
    float re = 0.f, im = 0.f;
#pragma unroll
    for (int w = 0; w < 64; w++) {
        float v = sx[r][w]; float2 t = tw[w][k];
        re += v*t.x; im += v*t.y;
    }
    g_a[(row0 + r)*MD + k] = make_float2(re, im);
}

// ---------------- forward y: 64 -> 16 modes (per (b,c,d)) ----------------
__global__ void k_fy() {
    __shared__ float2 sa[64][MD];
    __shared__ float2 tw[64][M2];
    int tid = threadIdx.x;  // 128
    int bcd = blockIdx.x;   // B*C*64 = 8192
    for (int i = tid; i < 64*M2; i += 128) {
        int h = i >> 4, j = i & 15;
        int ky = (j < 8) ? j : j + 48;
        float s, c; sincosf(((ky*h)&63)*PI2_64, &s, &c);
        tw[h][j] = make_float2(c, -s);
    }
    const float2* src = g_a + (size_t)bcd*64*MD;
    for (int i = tid; i < 64*MD; i += 128) sa[i>>3][i&7] = src[i];
    __syncthreads();
    int j = tid >> 3, k = tid & 7;
    float re = 0.f, im = 0.f;
#pragma unroll
    for (int h = 0; h < 64; h++) {
        float2 a = sa[h][k], t = tw[h][j];
        re += a.x*t.x - a.y*t.y;
        im += a.x*t.y + a.y*t.x;
    }
    g_b[((size_t)bcd*M2 + j)*MD + k] = make_float2(re, im);
}

// ---------------- forward x: 64 -> 16 modes (per (b,c,k)) ----------------
__global__ void k_fx() {
    __shared__ float2 sa[64][M2];
    __shared__ float2 tw[64][M2];
    int tid = threadIdx.x;  // 256
    int bc = blockIdx.x >> 3, k = blockIdx.x & 7;  // B*C*8 = 1024 blocks
    for (int i = tid; i < 64*M2; i += 256) {
        int d = i >> 4, ii = i & 15;
        int kx = (ii < 8) ? ii : ii + 48;
        float s, c; sincosf(((kx*d)&63)*PI2_64, &s, &c);
        tw[d][ii] = make_float2(c, -s);
    }
    const float2* src = g_b + (size_t)bc*64*M2*MD + k;
    for (int i = tid; i < 64*M2; i += 256) sa[i>>4][i&15] = src[(size_t)i*MD];
    __syncthreads();
    int i_ = tid >> 4, j = tid & 15;
    float re = 0.f, im = 0.f;
#pragma unroll
    for (int d = 0; d < 64; d++) {
        float2 a = sa[d][j], t = tw[d][i_];
        re += a.x*t.x - a.y*t.y;
        im += a.x*t.y + a.y*t.x;
    }
    g_ft[(((size_t)bc*M2 + i_)*M2 + j)*MD + k] = make_float2(re, im);
}

// ---------------- spectral channel mix: per mode 32x32 complex ----------------
__global__ void k_spec(const float* __restrict__ spw, int layer) {
    __shared__ float2 sw[CW][CW];
    __shared__ float2 sa[BN][CW];
    int tid = threadIdx.x;      // 128
    int mode = blockIdx.x;      // 2048 = (i*16+j)*8+k
    int k = mode & 7, j = (mode >> 3) & 15, i = mode >> 7;
    int corner = (i >= 8 ? 1 : 0) + (j >= 8 ? 2 : 0);
    int m1 = i & 7, m2 = j & 7;
    const float* wbase = spw + ((size_t)(layer*4 + corner)*CW*CW*512
                               + (size_t)(m1*64 + m2*8 + k)) * 2;
    for (int t = tid; t < CW*CW; t += 128)
        sw[t>>5][t&31] = *(const float2*)(wbase + (size_t)t*1024);
    for (int t = tid; t < BN*CW; t += 128) {
        int b = t >> 5, c = t & 31;
        sa[b][c] = g_ft[(((size_t)(b*CW+c)*M2 + i)*M2 + j)*MD + k];
    }
    __syncthreads();
    int b = tid >> 5, o = tid & 31;
    float re = 0.f, im = 0.f;
#pragma unroll
    for (int c = 0; c < CW; c++) {
        float2 a = sa[b][c], w = sw[c][o];
        re += a.x*w.x - a.y*w.y;
        im += a.x*w.y + a.y*w.x;
    }
    g_sf[(((size_t)(b*CW+o)*M2 + i)*M2 + j)*MD + k] = make_float2(re, im);
}

// ---------------- inverse x: 16 modes -> 64 (per (b,o,k)) ----------------
__global__ void k_ix() {
    __shared__ float2 sa[M2][M2];
    __shared__ float2 tw[64][M2];
    int tid = threadIdx.x;  // 256
    int bo = blockIdx.x >> 3, k = blockIdx.x & 7;  // 1024 blocks
    for (int t = tid; t < 64*M2; t += 256) {
        int d = t >> 4, ii = t & 15;
        int kx = (ii < 8) ? ii : ii + 48;
        float s, c; sincosf(((kx*d)&63)*PI2_64, &s, &c);
        tw[d][ii] = make_float2(c, s);
    }
    const float2* src = g_sf + (size_t)bo*M2*M2*MD + k;
    for (int t = tid; t < M2*M2; t += 256) sa[t>>4][t&15] = src[(size_t)t*MD];
    __syncthreads();
    for (int t = tid; t < 64*M2; t += 256) {
        int d = t >> 4, j = t & 15;
        float re = 0.f, im = 0.f;
#pragma unroll
        for (int ii = 0; ii < M2; ii++) {
            float2 a = sa[ii][j], w = tw[d][ii];
            re += a.x*w.x - a.y*w.y;
            im += a.x*w.y + a.y*w.x;
        }
        g_b[(((size_t)bo*64 + d)*M2 + j)*MD + k] = make_float2(re, im);
    }
}

// ---------------- inverse y: 16 modes -> 64 (per (b,o,d)) ----------------
__global__ void k_iy() {
    __shared__ float2 sa[M2][MD];
    __shared__ float2 tw[64][M2];
    int tid = threadIdx.x;  // 128
    int bod = blockIdx.x;   // 8192
    for (int t = tid; t < 64*M2; t += 128) {
        int h = t >> 4, j = t & 15;
        int ky = (j < 8) ? j : j + 48;
        float s, c; sincosf(((ky*h)&63)*PI2_64, &s, &c);
        tw[h][j] = make_float2(c, s);
    }
    const float2* src = g_b + (size_t)bod*M2*MD;
    for (int t = tid; t < M2*MD; t += 128) sa[t>>3][t&7] = src[t];
    __syncthreads();
    for (int t = tid; t < 64*MD; t += 128) {
        int h = t >> 3, k = t & 7;
        float re = 0.f, im = 0.f;
#pragma unroll
        for (int j = 0; j < M2; j++) {
            float2 a = sa[j][k], w = tw[h][j];
            re += a.x*w.x - a.y*w.y;
            im += a.x*w.y + a.y*w.x;
        }
        g_a[((size_t)bod*64 + h)*MD + k] = make_float2(re, im);
    }
}

// ---------------- layer update: irfft-z + pointwise + bias (+ gelu) ----------------
__global__ void k_layer(const float* __restrict__ wpw, const float* __restrict__ bpw,
                        int layer, int do_gelu, int flip) {
    __shared__ float  sx[CW][65];
    __shared__ float2 sz[CW][MD];
    __shared__ float  sw[CW][CW];
    __shared__ float  sb[CW];
    __shared__ float  crt[MD][64], cit[MD][64];
    const float* __restrict__ xin  = flip ? g_x1 : g_x0;
    float* __restrict__       xout = flip ? g_x0 : g_x1;
    int tid = threadIdx.x;  // 256
    int blk = blockIdx.x;   // B*4096 = 16384
    int b = blk >> 12, dh = blk & 4095;
    const float scale = 1.0f/262144.0f;
    for (int t = tid; t < MD*64; t += 256) {
        int k = t >> 6, w = t & 63;
        float s, c; sincosf(((k*w)&63)*PI2_64, &s, &c);
        crt[k][w] = (k == 0) ? scale : 2.f*scale*c;
        cit[k][w] = (k == 0) ? 0.f   : -2.f*scale*s;
    }
    for (int t = tid; t < CW*CW; t += 256) sw[t>>5][t&31] = wpw[(size_t)layer*CW*CW + t];
    if (tid < CW) sb[tid] = bpw[layer*CW + tid];
    for (int t = tid; t < CW*64; t += 256) {
        int c = t >> 6, w = t & 63;
        sx[c][w] = xin[((size_t)(b*CW+c)*4096 + dh)*64 + w];
    }
    for (int t = tid; t < CW*MD; t += 256) {
        int o = t >> 3, k = t & 7;
        sz[o][k] = g_a[((size_t)(b*CW+o)*4096 + dh)*MD + k];
    }
    __syncthreads();
    int w  = tid & 63;
    int o0 = (tid >> 6) * 8;
    float xr[CW];
#pragma unroll
    for (int c = 0; c < CW; c++) xr[c] = sx[c][w];
#pragma unroll
    for (int oi = 0; oi < 8; oi++) {
        int o = o0 + oi;
        float acc = sb[o];
#pragma unroll
        for (int c = 0; c < CW; c++) acc += xr[c]*sw[c][o];
#pragma unroll
        for (int k = 0; k < MD; k++) {
            float2 z = sz[o][k];
            acc += z.x*crt[k][w] + z.y*cit[k][w];
        }
        if (do_gelu) acc = gelu_tanh(acc);
        xout[((size_t)(b*CW+o)*4096 + dh)*64 + w] = acc;
    }
}

// ---------------- fused fc1 -> gelu -> fc2 head ----------------
__global__ void __launch_bounds__(256) k_fc(const float* __restrict__ w1,
                     const float* __restrict__ b1, const float* __restrict__ w2,
                     const float* __restrict__ b2, float* __restrict__ tau) {
    __shared__ float sw1[CW*FCHN];
    __shared__ float sw2[FCHN*6];
    __shared__ float sb1[FCHN];
    __shared__ float sb2[6];
    int tid = threadIdx.x;
    for (int t = tid; t < CW*FCHN; t += 256) sw1[t] = w1[t];
    for (int t = tid; t < FCHN*6;  t += 256) sw2[t] = w2[t];
    if (tid < FCHN) sb1[tid] = b1[tid];
    if (tid < 6)    sb2[tid] = b2[tid];
    __syncthreads();
    int base = blockIdx.x * 512;          // 2048 blocks, 2 points/thread
    int p0 = base + tid, p1 = base + tid + 256;
    int bb0 = p0 >> 18, s0 = p0 & (SP-1);
    int bb1 = p1 >> 18, s1 = p1 & (SP-1);
    float xa[CW], xb[CW];
#pragma unroll
    for (int c = 0; c < CW; c++) {
        xa[c] = g_x0[((bb0*CW + c) << 18) + s0];
        xb[c] = g_x0[((bb1*CW + c) << 18) + s1];
    }
    float ta[6], tb[6];
#pragma unroll
    for (int o = 0; o < 6; o++) { ta[o] = sb2[o]; tb[o] = sb2[o]; }
    for (int h = 0; h < FCHN; h++) {
        float a0 = sb1[h], a1 = sb1[h];
#pragma unroll
        for (int c = 0; c < CW; c++) {
            float wv = sw1[c*FCHN + h];
            a0 += xa[c]*wv; a1 += xb[c]*wv;
        }
        float g0 = gelu_tanh(a0);
        float g1 = gelu_tanh(a1);
#pragma unroll
        for (int o = 0; o < 6; o++) {
            float wv = sw2[h*6 + o];
            ta[o] += g0*wv; tb[o] += g1*wv;
        }
    }
#pragma unroll
    for (int o = 0; o < 6; o++) {
        tau[((bb0*6 + o) << 18) + s0] = ta[o];
        tau[((bb1*6 + o) << 18) + s1] = tb[o];
    }
}

// ---------------- hard NS core + 0.001*tau[:, :3] ----------------
__global__ void k_hard(const float* __restrict__ u, const float* __restrict__ tau,
                       float* __restrict__ out) {
    int idx = blockIdx.x*blockDim.x + threadIdx.x;
    if (idx >= BN*SP) return;
    int b = idx >> 18, s = idx & (SP-1);
    int d = s >> 12, h = (s >> 6) & 63, w = s & 63;
    const float dx = 2.0f*3.14159265358979323846f/64.0f;
    const float inv2dx = 1.0f/(2.0f*dx);
    const float invdx2 = 1.0f/(dx*dx);
    int dp = (((d+1)&63)<<12) | (h<<6) | w;
    int dm = (((d+63)&63)<<12) | (h<<6) | w;
    int hp = (d<<12) | (((h+1)&63)<<6) | w;
    int hm = (d<<12) | (((h+63)&63)<<6) | w;
    int wp = (d<<12) | (h<<6) | ((w+1)&63);
    int wm = (d<<12) | (h<<6) | ((w+63)&63);
    const float* ub = u + ((size_t)b*3 << 18);
    float uc[3];
#pragma unroll
    for (int i = 0; i < 3; i++) uc[i] = ub[(i<<18) + s];
#pragma unroll
    for (int i = 0; i < 3; i++) {
        const float* ui = ub + (i<<18);
        float xp = ui[dp], xm = ui[dm];
        float yp = ui[hp], ym = ui[hm];
        float zp = ui[wp], zm = ui[wm];
        float conv = -( uc[0]*(xp-xm) + uc[1]*(yp-ym) + uc[2]*(zp-zm) )*inv2dx;
        float lap  = (xp+xm+yp+ym+zp+zm - 6.f*uc[i])*invdx2;
        out[((size_t)(b*3+i)<<18) + s] = conv + 0.000185f*lap
                                       + 0.001f*tau[((size_t)(b*6+i)<<18) + s];
    }
}

extern "C" void kernel_launch(void* const* d_in, const int* in_sizes, int n_in,
                              void* d_out, int out_size) {
    (void)in_sizes; (void)n_in; (void)out_size;
    const float* u      = (const float*)d_in[0];
    const float* fc0_w  = (const float*)d_in[1];
    const float* fc0_b  = (const float*)d_in[2];
    const float* spec_w = (const float*)d_in[3];
    const float* w_pw   = (const float*)d_in[4];
    const float* b_pw   = (const float*)d_in[5];
    const float* fc1_w  = (const float*)d_in[6];
    const float* fc1_b  = (const float*)d_in[7];
    const float* fc2_w  = (const float*)d_in[8];
    const float* fc2_b  = (const float*)d_in[9];
    float* out = (float*)d_out;
    float* tau = out + (size_t)BN*3*SP;   // du_dt first, then tau

    k_fc0<<<(BN*SP + 255)/256, 256>>>(u, fc0_w, fc0_b);
    for (int l = 0; l < NLY; l++) {
        int flip = l & 1;  // input buffer: 0 -> g_x0, 1 -> g_x1
        k_fz  <<<BN*CW*RR*RR/16, 128>>>(flip);
        k_fy  <<<BN*CW*RR,       128>>>();
        k_fx  <<<BN*CW*MD,       256>>>();
        k_spec<<<M2*M2*MD,       128>>>(spec_w, l);
        k_ix  <<<BN*CW*MD,       256>>>();
        k_iy  <<<BN*CW*RR,       128>>>();
        k_layer<<<BN*RR*RR,      256>>>(w_pw, b_pw, l, (l < NLY-1) ? 1 : 0, flip);
    }
    // after 4 layers (0->x1, 1->x0, 2->x1, 3->x0) final activations are in g_x0
    k_fc  <<<BN*SP/512, 256>>>(fc1_w, fc1_b, fc2_w, fc2_b, tau);
    k_hard<<<(BN*SP + 255)/256, 256>>>(u, tau, out);
}

// round 2
// speedup vs baseline: 1.6469x; 1.6469x over previous
#include <cuda_runtime.h>
#include <math.h>

#define BN 4
#define CW 32
#define RR 64
#define SP (RR*RR*RR)        // 262144
#define MD 8
#define M2 16
#define NLY 4
#define FCHN 128
#define PI2_64 0.09817477042468103f   // 2*pi/64

// ---------------- scratch (static device memory; no allocation) ----------------
__device__ float  g_x0[BN*CW*SP];               // 134 MB
__device__ float  g_x1[BN*CW*SP];               // 134 MB
__device__ float2 g_a [BN*CW*RR*RR*MD];         // 33.5 MB  (fwd-z out / inv-y out)
__device__ float2 g_b [BN*CW*RR*M2*MD];         // 8.4 MB
__device__ float2 g_ft[BN*CW*M2*M2*MD];         // 2 MB
__device__ float2 g_sf[BN*CW*M2*M2*MD];         // 2 MB

__device__ __forceinline__ float gelu_fast(float a) {
    // 0.5*a*(1+tanh(y)) = a * sigmoid(2y),  2y = 1.59576912*(a + 0.044715 a^3)
    float z = 1.5957691216057308f * (a + 0.044715f*a*a*a);
    float e;
    asm("ex2.approx.f32 %0, %1;" : "=f"(e) : "f"(-1.4426950408889634f*z));
    float r;
    asm("rcp.approx.f32 %0, %1;" : "=f"(r) : "f"(1.0f + e));
    return a * r;
}

// ---------------- fc0 + fused forward-z DFT ----------------
// block = (b, dh);  writes g_x0 row (32 x 64) and g_a modes (32 x 8)
__global__ void k_fc0(const float* __restrict__ u, const float* __restrict__ w,
                      const float* __restrict__ bias) {
    __shared__ float  su[3][64];
    __shared__ float  sw[3*CW], sb[CW];
    __shared__ float  sxo[CW][65];
    __shared__ float2 twf[64][MD];
    int tid = threadIdx.x;  // 256
    int blk = blockIdx.x;   // BN*4096
    int b = blk >> 12, dh = blk & 4095;
    for (int t = tid; t < 64*MD; t += 256) {
        int ww = t >> 3, k = t & 7;
        float s, c; sincosf(((ww*k)&63)*PI2_64, &s, &c);
        twf[ww][k] = make_float2(c, -s);
    }
    if (tid < 3*CW) sw[tid] = w[tid];
    if (tid < CW)   sb[tid] = bias[tid];
    if (tid < 192) {
        int j = tid >> 6, ww = tid & 63;
        su[j][ww] = u[((size_t)(b*3+j) << 18) + dh*64 + ww];
    }
    __syncthreads();
    {
        int ww = tid & 63, o0 = (tid >> 6)*8;
        float u0 = su[0][ww], u1 = su[1][ww], u2 = su[2][ww];
#pragma unroll
        for (int oi = 0; oi < 8; oi++) {
            int o = o0 + oi;
            float acc = sb[o] + u0*sw[o] + u1*sw[CW+o] + u2*sw[2*CW+o];
            sxo[o][ww] = acc;
            g_x0[((size_t)(b*CW+o) << 18) + dh*64 + ww] = acc;
        }
    }
    __syncthreads();
    {
        int o = tid >> 3, k = tid & 7;
        float re = 0.f, im = 0.f;
#pragma unroll
        for (int ww = 0; ww < 64; ww++) {
            float v = sxo[o][ww]; float2 t = twf[ww][k];
            re += v*t.x; im += v*t.y;
        }
        g_a[((size_t)((b*CW+o)*4096 + dh))*MD + k] = make_float2(re, im);
    }
}

// ---------------- forward y: 64 -> 16 modes (per (b,c,d)) ----------------
__global__ void k_fy() {
    __shared__ float2 sa[64][MD];
    __shared__ float2 tw[64][M2];
    int tid = threadIdx.x;  // 128
    int bcd = blockIdx.x;   // B*C*64 = 8192
    for (int i = tid; i < 64*M2; i += 128) {
        int h = i >> 4, j = i & 15;
        int ky = (j < 8) ? j : j + 48;
        float s, c; sincosf(((ky*h)&63)*PI2_64, &s, &c);
        tw[h][j] = make_float2(c, -s);
    }
    const float2* src = g_a + (size_t)bcd*64*MD;
    for (int i = tid; i < 64*MD; i += 128) sa[i>>3][i&7] = src[i];
    __syncthreads();
    int j = tid >> 3, k = tid & 7;
    float re = 0.f, im = 0.f;
#pragma unroll
    for (int h = 0; h < 64; h++) {
        float2 a = sa[h][k], t = tw[h][j];
        re += a.x*t.x - a.y*t.y;
        im += a.x*t.y + a.y*t.x;
    }
    g_b[((size_t)bcd*M2 + j)*MD + k] = make_float2(re, im);
}

// ---------------- forward x: 64 -> 16 modes (per (b,c,k)) ----------------
__global__ void k_fx() {
    __shared__ float2 sa[64][M2];
    __shared__ float2 tw[64][M2];
    int tid = threadIdx.x;  // 256
    int bc = blockIdx.x >> 3, k = blockIdx.x & 7;  // 1024 blocks
    for (int i = tid; i < 64*M2; i += 256) {
        int d = i >> 4, ii = i & 15;
        int kx = (ii < 8) ? ii : ii + 48;
        float s, c; sincosf(((kx*d)&63)*PI2_64, &s, &c);
        tw[d][ii] = make_float2(c, -s);
    }
    const float2* src = g_b + (size_t)bc*64*M2*MD + k;
    for (int i = tid; i < 64*M2; i += 256) sa[i>>4][i&15] = src[(size_t)i*MD];
    __syncthreads();
    int i_ = tid >> 4, j = tid & 15;
    float re = 0.f, im = 0.f;
#pragma unroll
    for (int d = 0; d < 64; d++) {
        float2 a = sa[d][j], t = tw[d][i_];
        re += a.x*t.x - a.y*t.y;
        im += a.x*t.y + a.y*t.x;
    }
    g_ft[(((size_t)bc*M2 + i_)*M2 + j)*MD + k] = make_float2(re, im);
}

// ---------------- spectral channel mix: coalesced weights ----------------
// block = (i,j) mode pair (256 blocks), thread = (b,o) (128 threads)
__global__ void k_spec(const float* __restrict__ spw, int layer) {
    __shared__ float2 sa[BN][CW][MD];   // 8 KB
    int tid = threadIdx.x;
    int ij = blockIdx.x;
    int i = ij >> 4, j = ij & 15;
    int corner = (i >= 8 ? 1 : 0) + (j >= 8 ? 2 : 0);
    int m1 = i & 7, m2 = j & 7;
    for (int t = tid; t < BN*CW; t += 128) {
        int b = t >> 5, c = t & 31;
        const float4* src = (const float4*)&g_ft[(((size_t)(b*CW+c)*M2 + i)*M2 + j)*MD];
        float4* dst = (float4*)&sa[b][c][0];
        dst[0] = src[0]; dst[1] = src[1]; dst[2] = src[2]; dst[3] = src[3];
    }
    __syncthreads();
    int b = tid >> 5, o = tid & 31;
    const float* wbase = spw + ((size_t)(layer*4 + corner)*CW*CW*512
                               + (size_t)(m1*64 + m2*8)) * 2;
    float accr[MD], acci[MD];
#pragma unroll
    for (int k = 0; k < MD; k++) { accr[k] = 0.f; acci[k] = 0.f; }
#pragma unroll 4
    for (int c = 0; c < CW; c++) {
        const float4* wv = (const float4*)(wbase + (size_t)(c*32 + o)*1024);
        float4 w0 = wv[0], w1 = wv[1], w2 = wv[2], w3 = wv[3];
        const float4* av = (const float4*)&sa[b][c][0];
        float4 a0 = av[0], a1 = av[1], a2 = av[2], a3 = av[3];
        accr[0] += a0.x*w0.x - a0.y*w0.y;  acci[0] += a0.x*w0.y + a0.y*w0.x;
        accr[1] += a0.z*w0.z - a0.w*w0.w;  acci[1] += a0.z*w0.w + a0.w*w0.z;
        accr[2] += a1.x*w1.x - a1.y*w1.y;  acci[2] += a1.x*w1.y + a1.y*w1.x;
        accr[3] += a1.z*w1.z - a1.w*w1.w;  acci[3] += a1.z*w1.w + a1.w*w1.z;
        accr[4] += a2.x*w2.x - a2.y*w2.y;  acci[4] += a2.x*w2.y + a2.y*w2.x;
        accr[5] += a2.z*w2.z - a2.w*w2.w;  acci[5] += a2.z*w2.w + a2.w*w2.z;
        accr[6] += a3.x*w3.x - a3.y*w3.y;  acci[6] += a3.x*w3.y + a3.y*w3.x;
        accr[7] += a3.z*w3.z - a3.w*w3.w;  acci[7] += a3.z*w3.w + a3.w*w3.z;
    }
    float2* out = &g_sf[(((size_t)(b*CW+o)*M2 + i)*M2 + j)*MD];
#pragma unroll
    for (int k = 0; k < MD; k++) out[k] = make_float2(accr[k], acci[k]);
}

// ---------------- inverse x: 16 modes -> 64 (per (b,o,k)) ----------------
__global__ void k_ix() {
    __shared__ float2 sa[M2][M2];
    __shared__ float2 tw[64][M2];
    int tid = threadIdx.x;  // 256
    int bo = blockIdx.x >> 3, k = blockIdx.x & 7;  // 1024 blocks
    for (int t = tid; t < 64*M2; t += 256) {
        int d = t >> 4, ii = t & 15;
        int kx = (ii < 8) ? ii : ii + 48;
        float s, c; sincosf(((kx*d)&63)*PI2_64, &s, &c);
        tw[d][ii] = make_float2(c, s);
    }
    const float2* src = g_sf + (size_t)bo*M2*M2*MD + k;
    for (int t = tid; t < M2*M2; t += 256) sa[t>>4][t&15] = src[(size_t)t*MD];
    __syncthreads();
    for (int t = tid; t < 64*M2; t += 256) {
        int d = t >> 4, j = t & 15;
        float re = 0.f, im = 0.f;
#pragma unroll
        for (int ii = 0; ii < M2; ii++) {
            float2 a = sa[ii][j], w = tw[d][ii];
            re += a.x*w.x - a.y*w.y;
            im += a.x*w.y + a.y*w.x;
        }
        g_b[(((size_t)bo*64 + d)*M2 + j)*MD + k] = make_float2(re, im);
    }
}

// ---------------- inverse y: 16 modes -> 64 (per (b,o,d)) ----------------
__global__ void k_iy() {
    __shared__ float2 sa[M2][MD];
    __shared__ float2 tw[64][M2];
    int tid = threadIdx.x;  // 128
    int bod = blockIdx.x;   // 8192
    for (int t = tid; t < 64*M2; t += 128) {
        int h = t >> 4, j = t & 15;
        int ky = (j < 8) ? j : j + 48;
        float s, c; sincosf(((ky*h)&63)*PI2_64, &s, &c);
        tw[h][j] = make_float2(c, s);
    }
    const float2* src = g_b + (size_t)bod*M2*MD;
    for (int t = tid; t < M2*MD; t += 128) sa[t>>3][t&7] = src[t];
    __syncthreads();
    for (int t = tid; t < 64*MD; t += 128) {
        int h = t >> 3, k = t & 7;
        float re = 0.f, im = 0.f;
#pragma unroll
        for (int j = 0; j < M2; j++) {
            float2 a = sa[j][k], w = tw[h][j];
            re += a.x*w.x - a.y*w.y;
            im += a.x*w.y + a.y*w.x;
        }
        g_a[((size_t)bod*64 + h)*MD + k] = make_float2(re, im);
    }
}

// ---------------- layer update: irfft-z + pointwise (+gelu) + fused fwd-z ----------------
__global__ void k_layer(const float* __restrict__ wpw, const float* __restrict__ bpw,
                        int layer, int do_gelu, int flip, int do_fz) {
    __shared__ float  sx[CW][65];           // input x, later reused for output x
    __shared__ float2 sz[CW][MD];
    __shared__ float  sw[CW][CW];
    __shared__ float  sb[CW];
    __shared__ float  crt[MD][64], cit[MD][64];
    __shared__ float2 twf[64][MD];
    const float* __restrict__ xin  = flip ? g_x1 : g_x0;
    float* __restrict__       xout = flip ? g_x0 : g_x1;
    int tid = threadIdx.x;  // 256
    int blk = blockIdx.x;   // B*4096
    int b = blk >> 12, dh = blk & 4095;
    const float scale = 1.0f/262144.0f;
    for (int t = tid; t < MD*64; t += 256) {
        int k = t >> 6, ww = t & 63;
        float s, c; sincosf(((k*ww)&63)*PI2_64, &s, &c);
        crt[k][ww] = (k == 0) ? scale : 2.f*scale*c;
        cit[k][ww] = (k == 0) ? 0.f   : -2.f*scale*s;
        twf[ww][k] = make_float2(c, -s);   // same phases, fwd sign
    }
    for (int t = tid; t < CW*CW; t += 256) sw[t>>5][t&31] = wpw[(size_t)layer*CW*CW + t];
    if (tid < CW) sb[tid] = bpw[layer*CW + tid];
    for (int t = tid; t < CW*64; t += 256) {
        int c = t >> 6, ww = t & 63;
        sx[c][ww] = xin[((size_t)(b*CW+c)*4096 + dh)*64 + ww];
    }
    for (int t = tid; t < CW*MD; t += 256) {
        int o = t >> 3, k = t & 7;
        sz[o][k] = g_a[((size_t)(b*CW+o)*4096 + dh)*MD + k];
    }
    __syncthreads();
    int ww = tid & 63;
    int o0 = (tid >> 6) * 8;
    float xr[CW];
#pragma unroll
    for (int c = 0; c < CW; c++) xr[c] = sx[c][ww];
    __syncthreads();   // everyone has registers; sx may now be overwritten
#pragma unroll
    for (int oi = 0; oi < 8; oi++) {
        int o = o0 + oi;
        float acc = sb[o];
#pragma unroll
        for (int c = 0; c < CW; c++) acc += xr[c]*sw[c][o];
#pragma unroll
        for (int k = 0; k < MD; k++) {
            float2 z = sz[o][k];
            acc += z.x*crt[k][ww] + z.y*cit[k][ww];
        }
        if (do_gelu) acc = gelu_fast(acc);
        sx[o][ww] = acc;
        xout[((size_t)(b*CW+o)*4096 + dh)*64 + ww] = acc;
    }
    if (do_fz) {
        __syncthreads();
        int o = tid >> 3, k = tid & 7;
        float re = 0.f, im = 0.f;
#pragma unroll
        for (int w2 = 0; w2 < 64; w2++) {
            float v = sx[o][w2]; float2 t = twf[w2][k];
            re += v*t.x; im += v*t.y;
        }
        g_a[((size_t)(b*CW+o)*4096 + dh)*MD + k] = make_float2(re, im);
    }
}

// ---------------- fused fc1 -> gelu -> fc2 head (2 pts/thread) ----------------
__global__ void __launch_bounds__(256) k_fc(const float* __restrict__ w1,
                     const float* __restrict__ b1, const float* __restrict__ w2,
                     const float* __restrict__ b2, float* __restrict__ tau) {
    __shared__ float sw1t[FCHN*CW];   // transposed: [h][c]
    __shared__ float sw2[FCHN*6];
    __shared__ float sb1[FCHN];
    __shared__ float sb2[6];
    int tid = threadIdx.x;
    for (int t = tid; t < FCHN*CW; t += 256) {
        int h = t >> 5, c = t & 31;
        sw1t[t] = w1[c*FCHN + h];
    }
    for (int t = tid; t < FCHN*6;  t += 256) sw2[t] = w2[t];
    if (tid < FCHN) sb1[tid] = b1[tid];
    if (tid < 6)    sb2[tid] = b2[tid];
    __syncthreads();
    int p0 = blockIdx.x*512 + tid*2;      // 2048 blocks, 2 consecutive pts/thread
    int b = p0 >> 18, s = p0 & (SP-1);
    float2 xa[CW];
#pragma unroll
    for (int c = 0; c < CW; c++)
        xa[c] = *(const float2*)&g_x0[(((size_t)b*CW + c) << 18) + s];
    float ta[6], tb[6];
#pragma unroll
    for (int o = 0; o < 6; o++) { ta[o] = sb2[o]; tb[o] = sb2[o]; }
    for (int h = 0; h < FCHN; h++) {
        const float4* wt = (const float4*)&sw1t[h*CW];
        float a0 = sb1[h], a1 = a0;
#pragma unroll
        for (int cq = 0; cq < 8; cq++) {
            float4 w = wt[cq];
            float2 v0 = xa[cq*4+0]; a0 += v0.x*w.x; a1 += v0.y*w.x;
            float2 v1 = xa[cq*4+1]; a0 += v1.x*w.y; a1 += v1.y*w.y;
            float2 v2 = xa[cq*4+2]; a0 += v2.x*w.z; a1 += v2.y*w.z;
            float2 v3 = xa[cq*4+3]; a0 += v3.x*w.w; a1 += v3.y*w.w;
        }
        float g0 = gelu_fast(a0);
        float g1 = gelu_fast(a1);
#pragma unroll
        for (int o = 0; o < 6; o++) {
            float wv = sw2[h*6 + o];
            ta[o] += g0*wv; tb[o] += g1*wv;
        }
    }
#pragma unroll
    for (int o = 0; o < 6; o++) {
        *(float2*)&tau[(((size_t)b*6 + o) << 18) + s] = make_float2(ta[o], tb[o]);
    }
}

// ---------------- hard NS core + 0.001*tau[:, :3] ----------------
__global__ void k_hard(const float* __restrict__ u, const float* __restrict__ tau,
                       float* __restrict__ out) {
    int idx = blockIdx.x*blockDim.x + threadIdx.x;
    if (idx >= BN*SP) return;
    int b = idx >> 18, s = idx & (SP-1);
    int d = s >> 12, h = (s >> 6) & 63, w = s & 63;
    const float dx = 2.0f*3.14159265358979323846f/64.0f;
    const float inv2dx = 1.0f/(2.0f*dx);
    const float invdx2 = 1.0f/(dx*dx);
    int dp = (((d+1)&63)<<12) | (h<<6) | w;
    int dm = (((d+63)&63)<<12) | (h<<6) | w;
    int hp = (d<<12) | (((h+1)&63)<<6) | w;
    int hm = (d<<12) | (((h+63)&63)<<6) | w;
    int wp = (d<<12) | (h<<6) | ((w+1)&63);
    int wm = (d<<12) | (h<<6) | ((w+63)&63);
    const float* ub = u + ((size_t)b*3 << 18);
    float uc[3];
#pragma unroll
    for (int i = 0; i < 3; i++) uc[i] = ub[(i<<18) + s];
#pragma unroll
    for (int i = 0; i < 3; i++) {
        const float* ui = ub + (i<<18);
        float xp = ui[dp], xm = ui[dm];
        float yp = ui[hp], ym = ui[hm];
        float zp = ui[wp], zm = ui[wm];
        float conv = -( uc[0]*(xp-xm) + uc[1]*(yp-ym) + uc[2]*(zp-zm) )*inv2dx;
        float lap  = (xp+xm+yp+ym+zp+zm - 6.f*uc[i])*invdx2;
        out[((size_t)(b*3+i)<<18) + s] = conv + 0.000185f*lap
                                       + 0.001f*tau[((size_t)(b*6+i)<<18) + s];
    }
}

extern "C" void kernel_launch(void* const* d_in, const int* in_sizes, int n_in,
                              void* d_out, int out_size) {
    (void)in_sizes; (void)n_in; (void)out_size;
    const float* u      = (const float*)d_in[0];
    const float* fc0_w  = (const float*)d_in[1];
    const float* fc0_b  = (const float*)d_in[2];
    const float* spec_w = (const float*)d_in[3];
    const float* w_pw   = (const float*)d_in[4];
    const float* b_pw   = (const float*)d_in[5];
    const float* fc1_w  = (const float*)d_in[6];
    const float* fc1_b  = (const float*)d_in[7];
    const float* fc2_w  = (const float*)d_in[8];
    const float* fc2_b  = (const float*)d_in[9];
    float* out = (float*)d_out;
    float* tau = out + (size_t)BN*3*SP;   // du_dt first, then tau

    k_fc0<<<BN*RR*RR, 256>>>(u, fc0_w, fc0_b);   // writes g_x0 + g_a (fwd-z)
    for (int l = 0; l < NLY; l++) {
        int flip = l & 1;  // input buffer: 0 -> g_x0, 1 -> g_x1
        k_fy  <<<BN*CW*RR, 128>>>();
        k_fx  <<<BN*CW*MD, 256>>>();
        k_spec<<<M2*M2,    128>>>(spec_w, l);
        k_ix  <<<BN*CW*MD, 256>>>();
        k_iy  <<<BN*CW*RR, 128>>>();
        k_layer<<<BN*RR*RR, 256>>>(w_pw, b_pw, l,
                                   (l < NLY-1) ? 1 : 0, flip,
                                   (l < NLY-1) ? 1 : 0);
    }
    // after 4 layers (0->x1, 1->x0, 2->x1, 3->x0) final activations are in g_x0
    k_fc  <<<BN*SP/512, 256>>>(fc1_w, fc1_b, fc2_w, fc2_b, tau);
    k_hard<<<(BN*SP + 255)/256, 256>>>(u, tau, out);
}

// round 3
// speedup vs baseline: 1.9218x; 1.1670x over previous
#include <cuda_runtime.h>
#include <math.h>

#define BN 4
#define CW 32
#define RR 64
#define SP (RR*RR*RR)        // 262144
#define MD 8
#define M2 16
#define NLY 4
#define FCHN 128
#define PI2_64 0.09817477042468103f   // 2*pi/64

typedef unsigned long long u64t;

__device__ __forceinline__ u64t pk2(float lo, float hi) {
    u64t r; asm("mov.b64 %0, {%1,%2};" : "=l"(r) : "f"(lo), "f"(hi)); return r;
}
__device__ __forceinline__ u64t dup2(float v) { return pk2(v, v); }
__device__ __forceinline__ void up2(u64t v, float& a, float& b) {
    asm("mov.b64 {%0,%1}, %2;" : "=f"(a), "=f"(b) : "l"(v));
}
__device__ __forceinline__ void fma2(u64t& d, u64t a, u64t b) {
    asm("fma.rn.f32x2 %0, %1, %2, %0;" : "+l"(d) : "l"(a), "l"(b));
}

// ---------------- scratch (static device memory; no allocation) ----------------
__device__ float  g_x0[BN*CW*SP];               // 134 MB
__device__ float  g_x1[BN*CW*SP];               // 134 MB
__device__ float2 g_a [BN*CW*RR*RR*MD];         // 33.5 MB  (fwd-z out / inv-y out)
__device__ float2 g_b [BN*CW*RR*M2*MD];         // 8.4 MB
__device__ float2 g_ft[BN*CW*M2*M2*MD];         // 2 MB
__device__ float2 g_sf[BN*CW*M2*M2*MD];         // 2 MB

__device__ __forceinline__ float gelu_fast(float a) {
    // 0.5*a*(1+tanh(y)) = a * sigmoid(2y),  2y = 1.59576912*(a + 0.044715 a^3)
    float z = 1.5957691216057308f * (a + 0.044715f*a*a*a);
    float e;
    asm("ex2.approx.f32 %0, %1;" : "=f"(e) : "f"(-1.4426950408889634f*z));
    float r;
    asm("rcp.approx.f32 %0, %1;" : "=f"(r) : "f"(1.0f + e));
    return a * r;
}

// ---------------- fc0 + fused forward-z DFT ----------------
__global__ void k_fc0(const float* __restrict__ u, const float* __restrict__ w,
                      const float* __restrict__ bias) {
    __shared__ float  su[3][64];
    __shared__ float  sw[3*CW], sb[CW];
    __shared__ float  sxo[CW][65];
    __shared__ float2 twf[64][MD];
    int tid = threadIdx.x;  // 256
    int blk = blockIdx.x;   // BN*4096
    int b = blk >> 12, dh = blk & 4095;
    for (int t = tid; t < 64*MD; t += 256) {
        int ww = t >> 3, k = t & 7;
        float s, c; sincosf(((ww*k)&63)*PI2_64, &s, &c);
        twf[ww][k] = make_float2(c, -s);
    }
    if (tid < 3*CW) sw[tid] = w[tid];
    if (tid < CW)   sb[tid] = bias[tid];
    if (tid < 192) {
        int j = tid >> 6, ww = tid & 63;
        su[j][ww] = u[((size_t)(b*3+j) << 18) + dh*64 + ww];
    }
    __syncthreads();
    {
        int ww = tid & 63, o0 = (tid >> 6)*8;
#pragma unroll
        for (int oi = 0; oi < 8; oi++) {
            int o = o0 + oi;
            float acc = sb[o] + su[0][ww]*sw[o] + su[1][ww]*sw[CW+o] + su[2][ww]*sw[2*CW+o];
            sxo[o][ww] = acc;
            g_x0[((size_t)(b*CW+o) << 18) + dh*64 + ww] = acc;
        }
    }
    __syncthreads();
    {
        int o = tid >> 3, k = tid & 7;
        u64t zacc = 0ull;
#pragma unroll
        for (int ww = 0; ww < 64; ww++)
            fma2(zacc, dup2(sxo[o][ww]), *(const u64t*)&twf[ww][k]);
        float re, im; up2(zacc, re, im);
        g_a[((size_t)((b*CW+o)*4096 + dh))*MD + k] = make_float2(re, im);
    }
}

// ---------------- forward y: 64 -> 16 modes (per (b,c,d)) ----------------
__global__ void k_fy() {
    __shared__ float2 sa[64][MD];
    __shared__ float2 tw[64][M2];
    int tid = threadIdx.x;  // 128
    int bcd = blockIdx.x;   // 8192
    for (int i = tid; i < 64*M2; i += 128) {
        int h = i >> 4, j = i & 15;
        int ky = (j < 8) ? j : j + 48;
        float s, c; sincosf(((ky*h)&63)*PI2_64, &s, &c);
        tw[h][j] = make_float2(c, -s);
    }
    const float2* src = g_a + (size_t)bcd*64*MD;
    for (int i = tid; i < 64*MD; i += 128) sa[i>>3][i&7] = src[i];
    __syncthreads();
    int j = tid >> 3, k = tid & 7;
    float re = 0.f, im = 0.f;
#pragma unroll
    for (int h = 0; h < 64; h++) {
        float2 a = sa[h][k], t = tw[h][j];
        re += a.x*t.x - a.y*t.y;
        im += a.x*t.y + a.y*t.x;
    }
    g_b[((size_t)bcd*M2 + j)*MD + k] = make_float2(re, im);
}

// ---------------- forward x: 64 -> 16 modes (per (b,c,k)) ----------------
__global__ void k_fx() {
    __shared__ float2 sa[64][M2];
    __shared__ float2 tw[64][M2];
    int tid = threadIdx.x;  // 256
    int bc = blockIdx.x >> 3, k = blockIdx.x & 7;  // 1024 blocks
    for (int i = tid; i < 64*M2; i += 256) {
        int d = i >> 4, ii = i & 15;
        int kx = (ii < 8) ? ii : ii + 48;
        float s, c; sincosf(((kx*d)&63)*PI2_64, &s, &c);
        tw[d][ii] = make_float2(c, -s);
    }
    const float2* src = g_b + (size_t)bc*64*M2*MD + k;
    for (int i = tid; i < 64*M2; i += 256) sa[i>>4][i&15] = src[(size_t)i*MD];
    __syncthreads();
    int i_ = tid >> 4, j = tid & 15;
    float re = 0.f, im = 0.f;
#pragma unroll
    for (int d = 0; d < 64; d++) {
        float2 a = sa[d][j], t = tw[d][i_];
        re += a.x*t.x - a.y*t.y;
        im += a.x*t.y + a.y*t.x;
    }
    g_ft[(((size_t)bc*M2 + i_)*M2 + j)*MD + k] = make_float2(re, im);
}

// ---------------- spectral channel mix: block per (b,i,j), c-split 4 ----------------
__global__ void k_spec(const float* __restrict__ spw, int layer) {
    __shared__ float2 sa[CW][MD];        // 2 KB (this batch's modes)
    __shared__ float  red[4][CW][MD*2];  // 8 KB partials
    int tid = threadIdx.x;   // 128
    int blk = blockIdx.x;    // 1024 = b*256 + i*16 + j
    int b = blk >> 8, i = (blk >> 4) & 15, j = blk & 15;
    int corner = (i >= 8 ? 1 : 0) + (j >= 8 ? 2 : 0);
    int m1 = i & 7, m2 = j & 7;
    for (int t = tid; t < CW*MD; t += 128) {
        int c = t >> 3, k = t & 7;
        sa[c][k] = g_ft[(((size_t)(b*CW+c)*M2 + i)*M2 + j)*MD + k];
    }
    __syncthreads();
    int o = tid & 31, cq = tid >> 5;
    const float* wbase = spw + ((size_t)(layer*4 + corner)*CW*CW*512
                               + (size_t)(m1*64 + m2*8)) * 2;
    float accr[MD], acci[MD];
#pragma unroll
    for (int k = 0; k < MD; k++) { accr[k] = 0.f; acci[k] = 0.f; }
#pragma unroll
    for (int c8 = 0; c8 < 8; c8++) {
        int c = cq*8 + c8;
        const float4* wv = (const float4*)(wbase + (size_t)(c*32 + o)*1024);
        float4 w0 = wv[0], w1 = wv[1], w2 = wv[2], w3 = wv[3];
        const float4* av = (const float4*)&sa[c][0];
        float4 a0 = av[0], a1 = av[1], a2 = av[2], a3 = av[3];
        accr[0] += a0.x*w0.x - a0.y*w0.y;  acci[0] += a0.x*w0.y + a0.y*w0.x;
        accr[1] += a0.z*w0.z - a0.w*w0.w;  acci[1] += a0.z*w0.w + a0.w*w0.z;
        accr[2] += a1.x*w1.x - a1.y*w1.y;  acci[2] += a1.x*w1.y + a1.y*w1.x;
        accr[3] += a1.z*w1.z - a1.w*w1.w;  acci[3] += a1.z*w1.w + a1.w*w1.z;
        accr[4] += a2.x*w2.x - a2.y*w2.y;  acci[4] += a2.x*w2.y + a2.y*w2.x;
        accr[5] += a2.z*w2.z - a2.w*w2.w;  acci[5] += a2.z*w2.w + a2.w*w2.z;
        accr[6] += a3.x*w3.x - a3.y*w3.y;  acci[6] += a3.x*w3.y + a3.y*w3.x;
        accr[7] += a3.z*w3.z - a3.w*w3.w;  acci[7] += a3.z*w3.w + a3.w*w3.z;
    }
#pragma unroll
    for (int k = 0; k < MD; k++) {
        red[cq][o][2*k]   = accr[k];
        red[cq][o][2*k+1] = acci[k];
    }
    __syncthreads();
    float* gs = (float*)g_sf;
#pragma unroll
    for (int r = 0; r < 4; r++) {
        int idx = r*128 + tid;          // 512 outputs
        int o2 = idx >> 4, v = idx & 15;
        float s = red[0][o2][v] + red[1][o2][v] + red[2][o2][v] + red[3][o2][v];
        gs[((((size_t)(b*CW+o2)*M2 + i)*M2 + j)*MD)*2 + v] = s;
    }
}

// ---------------- inverse x: 16 modes -> 64 (per (b,o,k)) ----------------
__global__ void k_ix() {
    __shared__ float2 sa[M2][M2];
    __shared__ float2 tw[64][M2];
    int tid = threadIdx.x;  // 256
    int bo = blockIdx.x >> 3, k = blockIdx.x & 7;  // 1024 blocks
    for (int t = tid; t < 64*M2; t += 256) {
        int d = t >> 4, ii = t & 15;
        int kx = (ii < 8) ? ii : ii + 48;
        float s, c; sincosf(((kx*d)&63)*PI2_64, &s, &c);
        tw[d][ii] = make_float2(c, s);
    }
    const float2* src = g_sf + (size_t)bo*M2*M2*MD + k;
    for (int t = tid; t < M2*M2; t += 256) sa[t>>4][t&15] = src[(size_t)t*MD];
    __syncthreads();
    for (int t = tid; t < 64*M2; t += 256) {
        int d = t >> 4, j = t & 15;
        float re = 0.f, im = 0.f;
#pragma unroll
        for (int ii = 0; ii < M2; ii++) {
            float2 a = sa[ii][j], w = tw[d][ii];
            re += a.x*w.x - a.y*w.y;
            im += a.x*w.y + a.y*w.x;
        }
        g_b[(((size_t)bo*64 + d)*M2 + j)*MD + k] = make_float2(re, im);
    }
}

// ---------------- inverse y: 16 modes -> 64 (per (b,o,d)) ----------------
__global__ void k_iy() {
    __shared__ float2 sa[M2][MD];
    __shared__ float2 tw[64][M2];
    int tid = threadIdx.x;  // 128
    int bod = blockIdx.x;   // 8192
    for (int t = tid; t < 64*M2; t += 128) {
        int h = t >> 4, j = t & 15;
        int ky = (j < 8) ? j : j + 48;
        float s, c; sincosf(((ky*h)&63)*PI2_64, &s, &c);
        tw[h][j] = make_float2(c, s);
    }
    const float2* src = g_b + (size_t)bod*M2*MD;
    for (int t = tid; t < M2*MD; t += 128) sa[t>>3][t&7] = src[t];
    __syncthreads();
    for (int t = tid; t < 64*MD; t += 128) {
        int h = t >> 3, k = t & 7;
        float re = 0.f, im = 0.f;
#pragma unroll
        for (int j = 0; j < M2; j++) {
            float2 a = sa[j][k], w = tw[h][j];
            re += a.x*w.x - a.y*w.y;
            im += a.x*w.y + a.y*w.x;
        }
        g_a[((size_t)bod*64 + h)*MD + k] = make_float2(re, im);
    }
}

// ---------------- layer update (f32x2): irfft-z + pointwise (+gelu) + fwd-z ----------------
__global__ void k_layer(const float* __restrict__ wpw, const float* __restrict__ bpw,
                        int layer, int do_gelu, int flip, int do_fz) {
    __shared__ float  sx[CW][65];
    __shared__ float  szr[MD][CW], szi[MD][CW];
    __shared__ float  sw[CW][CW];
    __shared__ float  sb[CW];
    __shared__ float  crt[MD][64], cit[MD][64];
    __shared__ float2 twf[64][MD];
    const float* __restrict__ xin  = flip ? g_x1 : g_x0;
    float* __restrict__       xout = flip ? g_x0 : g_x1;
    int tid = threadIdx.x;  // 256
    int blk = blockIdx.x;   // B*4096
    int b = blk >> 12, dh = blk & 4095;
    const float scale = 1.0f/262144.0f;
    for (int t = tid; t < MD*64; t += 256) {
        int k = t >> 6, ww = t & 63;
        float s, c; sincosf(((k*ww)&63)*PI2_64, &s, &c);
        crt[k][ww] = (k == 0) ? scale : 2.f*scale*c;
        cit[k][ww] = (k == 0) ? 0.f   : -2.f*scale*s;
        twf[ww][k] = make_float2(c, -s);
    }
    for (int t = tid; t < CW*CW; t += 256) sw[t>>5][t&31] = wpw[(size_t)layer*CW*CW + t];
    if (tid < CW) sb[tid] = bpw[layer*CW + tid];
    for (int t = tid; t < CW*64; t += 256) {
        int c = t >> 6, ww = t & 63;
        sx[c][ww] = xin[((size_t)(b*CW+c)*4096 + dh)*64 + ww];
    }
    for (int t = tid; t < CW*MD; t += 256) {
        int o = t >> 3, k = t & 7;
        float2 z = g_a[((size_t)(b*CW+o)*4096 + dh)*MD + k];
        szr[k][o] = z.x; szi[k][o] = z.y;
    }
    __syncthreads();
    int ww = tid & 63;
    int o0 = (tid >> 6) * 8;
    float xr[CW];
#pragma unroll
    for (int c = 0; c < CW; c++) xr[c] = sx[c][ww];
    __syncthreads();   // sx free for reuse
    u64t acc[4];
#pragma unroll
    for (int p = 0; p < 4; p++) acc[p] = pk2(sb[o0+2*p], sb[o0+2*p+1]);
#pragma unroll
    for (int c = 0; c < CW; c++) {
        ulonglong2 w01 = *(const ulonglong2*)&sw[c][o0];
        ulonglong2 w23 = *(const ulonglong2*)&sw[c][o0+4];
        u64t xd = dup2(xr[c]);
        fma2(acc[0], xd, w01.x); fma2(acc[1], xd, w01.y);
        fma2(acc[2], xd, w23.x); fma2(acc[3], xd, w23.y);
    }
#pragma unroll
    for (int k = 0; k < MD; k++) {
        u64t cr = dup2(crt[k][ww]);
        u64t ci = dup2(cit[k][ww]);
#pragma unroll
        for (int p = 0; p < 4; p++) {
            u64t zr = *(const u64t*)&szr[k][o0+2*p];
            u64t zi = *(const u64t*)&szi[k][o0+2*p];
            fma2(acc[p], zr, cr);
            fma2(acc[p], zi, ci);
        }
    }
#pragma unroll
    for (int p = 0; p < 4; p++) {
        float v0, v1; up2(acc[p], v0, v1);
        if (do_gelu) { v0 = gelu_fast(v0); v1 = gelu_fast(v1); }
        sx[o0+2*p][ww]   = v0;
        sx[o0+2*p+1][ww] = v1;
        xout[((size_t)(b*CW+o0+2*p)*4096 + dh)*64 + ww]   = v0;
        xout[((size_t)(b*CW+o0+2*p+1)*4096 + dh)*64 + ww] = v1;
    }
    if (do_fz) {
        __syncthreads();
        int o = tid >> 3, k = tid & 7;
        u64t zacc = 0ull;
#pragma unroll
        for (int w2 = 0; w2 < 64; w2++)
            fma2(zacc, dup2(sx[o][w2]), *(const u64t*)&twf[w2][k]);
        float re, im; up2(zacc, re, im);
        g_a[((size_t)(b*CW+o)*4096 + dh)*MD + k] = make_float2(re, im);
    }
}

// ---------------- fused fc1 -> gelu -> fc2 head (f32x2, 2 pts/thread) ----------------
__global__ void __launch_bounds__(256) k_fc(const float* __restrict__ w1,
                     const float* __restrict__ b1, const float* __restrict__ w2,
                     const float* __restrict__ b2, float* __restrict__ tau) {
    __shared__ float2 sw1d[FCHN][CW];   // duplicated weights: 32 KB
    __shared__ float2 sw2d[FCHN][6];    // duplicated: 6 KB
    __shared__ float  sb1[FCHN];
    __shared__ float  sb2[6];
    int tid = threadIdx.x;
    for (int t = tid; t < FCHN*CW; t += 256) {
        int h = t >> 5, c = t & 31;
        float v = w1[c*FCHN + h];
        sw1d[h][c] = make_float2(v, v);
    }
    for (int t = tid; t < FCHN*6; t += 256) {
        float v = w2[t];
        sw2d[t/6][t%6] = make_float2(v, v);
    }
    if (tid < FCHN) sb1[tid] = b1[tid];
    if (tid < 6)    sb2[tid] = b2[tid];
    __syncthreads();
    int p0 = blockIdx.x*512 + tid*2;      // 2048 blocks, 2 consecutive pts/thread
    int b = p0 >> 18, s = p0 & (SP-1);
    u64t xa[CW];
#pragma unroll
    for (int c = 0; c < CW; c++)
        xa[c] = *(const u64t*)&g_x0[(((size_t)b*CW + c) << 18) + s];
    u64t tacc[6];
#pragma unroll
    for (int o = 0; o < 6; o++) tacc[o] = dup2(sb2[o]);
    for (int h = 0; h < FCHN; h++) {
        u64t a01 = dup2(sb1[h]);
        const ulonglong2* wd = (const ulonglong2*)&sw1d[h][0];
#pragma unroll
        for (int cp = 0; cp < 16; cp++) {
            ulonglong2 w = wd[cp];
            fma2(a01, xa[2*cp],   w.x);
            fma2(a01, xa[2*cp+1], w.y);
        }
        float a0, a1; up2(a01, a0, a1);
        u64t g01 = pk2(gelu_fast(a0), gelu_fast(a1));
#pragma unroll
        for (int o = 0; o < 6; o++)
            fma2(tacc[o], g01, *(const u64t*)&sw2d[h][o]);
    }
#pragma unroll
    for (int o = 0; o < 6; o++) {
        float ta, tb; up2(tacc[o], ta, tb);
        *(float2*)&tau[(((size_t)b*6 + o) << 18) + s] = make_float2(ta, tb);
    }
}

// ---------------- hard NS core + 0.001*tau[:, :3] ----------------
__global__ void k_hard(const float* __restrict__ u, const float* __restrict__ tau,
                       float* __restrict__ out) {
    int idx = blockIdx.x*blockDim.x + threadIdx.x;
    if (idx >= BN*SP) return;
    int b = idx >> 18, s = idx & (SP-1);
    int d = s >> 12, h = (s >> 6) & 63, w = s & 63;
    const float dx = 2.0f*3.14159265358979323846f/64.0f;
    const float inv2dx = 1.0f/(2.0f*dx);
    const float invdx2 = 1.0f/(dx*dx);
    int dp = (((d+1)&63)<<12) | (h<<6) | w;
    int dm = (((d+63)&63)<<12) | (h<<6) | w;
    int hp = (d<<12) | (((h+1)&63)<<6) | w;
    int hm = (d<<12) | (((h+63)&63)<<6) | w;
    int wp = (d<<12) | (h<<6) | ((w+1)&63);
    int wm = (d<<12) | (h<<6) | ((w+63)&63);
    const float* ub = u + ((size_t)b*3 << 18);
    float uc[3];
#pragma unroll
    for (int i = 0; i < 3; i++) uc[i] = ub[(i<<18) + s];
#pragma unroll
    for (int i = 0; i < 3; i++) {
        const float* ui = ub + (i<<18);
        float xp = ui[dp], xm = ui[dm];
        float yp = ui[hp], ym = ui[hm];
        float zp = ui[wp], zm = ui[wm];
        float conv = -( uc[0]*(xp-xm) + uc[1]*(yp-ym) + uc[2]*(zp-zm) )*inv2dx;
        float lap  = (xp+xm+yp+ym+zp+zm - 6.f*uc[i])*invdx2;
        out[((size_t)(b*3+i)<<18) + s] = conv + 0.000185f*lap
                                       + 0.001f*tau[((size_t)(b*6+i)<<18) + s];
    }
}

extern "C" void kernel_launch(void* const* d_in, const int* in_sizes, int n_in,
                              void* d_out, int out_size) {
    (void)in_sizes; (void)n_in; (void)out_size;
    const float* u      = (const float*)d_in[0];
    const float* fc0_w  = (const float*)d_in[1];
    const float* fc0_b  = (const float*)d_in[2];
    const float* spec_w = (const float*)d_in[3];
    const float* w_pw   = (const float*)d_in[4];
    const float* b_pw   = (const float*)d_in[5];
    const float* fc1_w  = (const float*)d_in[6];
    const float* fc1_b  = (const float*)d_in[7];
    const float* fc2_w  = (const float*)d_in[8];
    const float* fc2_b  = (const float*)d_in[9];
    float* out = (float*)d_out;
    float* tau = out + (size_t)BN*3*SP;   // du_dt first, then tau

    k_fc0<<<BN*RR*RR, 256>>>(u, fc0_w, fc0_b);   // writes g_x0 + g_a (fwd-z)
    for (int l = 0; l < NLY; l++) {
        int flip = l & 1;  // input buffer: 0 -> g_x0, 1 -> g_x1
        k_fy  <<<BN*CW*RR,   128>>>();
        k_fx  <<<BN*CW*MD,   256>>>();
        k_spec<<<BN*M2*M2,   128>>>(spec_w, l);
        k_ix  <<<BN*CW*MD,   256>>>();
        k_iy  <<<BN*CW*RR,   128>>>();
        k_layer<<<BN*RR*RR,  256>>>(w_pw, b_pw, l,
                                    (l < NLY-1) ? 1 : 0, flip,
                                    (l < NLY-1) ? 1 : 0);
    }
    // after 4 layers (0->x1, 1->x0, 2->x1, 3->x0) final activations are in g_x0
    k_fc  <<<BN*SP/512, 256>>>(fc1_w, fc1_b, fc2_w, fc2_b, tau);
    k_hard<<<(BN*SP + 255)/256, 256>>>(u, tau, out);
}

// round 4
// speedup vs baseline: 2.1851x; 1.1370x over previous
#include <cuda_runtime.h>
#include <math.h>

#define BN 4
#define CW 32
#define RR 64
#define SP (RR*RR*RR)        // 262144
#define MD 8
#define M2 16
#define NLY 4
#define FCHN 128
#define PI2_64 0.09817477042468103f   // 2*pi/64

typedef unsigned long long u64t;

__device__ __forceinline__ u64t pk2(float lo, float hi) {
    u64t r; asm("mov.b64 %0, {%1,%2};" : "=l"(r) : "f"(lo), "f"(hi)); return r;
}
__device__ __forceinline__ u64t dup2(float v) { return pk2(v, v); }
__device__ __forceinline__ void up2(u64t v, float& a, float& b) {
    asm("mov.b64 {%0,%1}, %2;" : "=f"(a), "=f"(b) : "l"(v));
}
__device__ __forceinline__ void fma2(u64t& d, u64t a, u64t b) {
    asm("fma.rn.f32x2 %0, %1, %2, %0;" : "+l"(d) : "l"(a), "l"(b));
}

// ---------------- scratch (static device memory; no allocation) ----------------
__device__ float  g_x0[BN*CW*SP];               // 134 MB
__device__ float  g_x1[BN*CW*SP];               // 134 MB
__device__ float2 g_a [BN*CW*RR*RR*MD];         // 33.5 MB
__device__ float2 g_b [BN*CW*RR*M2*MD];         // 8.4 MB
__device__ float2 g_ft[BN*CW*M2*M2*MD];         // 2 MB
__device__ float2 g_sf[BN*CW*M2*M2*MD];         // 2 MB

// precomputed twiddle tables
__device__ float2 g_twf_[64*MD];    // fwd z: (c,-s)  [ww][k]
__device__ float  g_crt_[MD*64];    // irfft z coef   [k][ww]
__device__ float  g_cit_[MD*64];
__device__ float2 g_twF_[64*M2];    // fwd y/x: (c,-s) [h][j], ky = j<8?j:j+48
__device__ float2 g_twI_[64*M2];    // inv y/x: (c, s)

__global__ void k_init() {
    int t = blockIdx.x*blockDim.x + threadIdx.x;
    if (t < 512) {
        int ww = t >> 3, k = t & 7;
        float s, c; sincosf(((ww*k)&63)*PI2_64, &s, &c);
        g_twf_[t] = make_float2(c, -s);
        const float scale = 1.0f/262144.0f;
        g_crt_[k*64+ww] = (k == 0) ? scale : 2.f*scale*c;
        g_cit_[k*64+ww] = (k == 0) ? 0.f   : -2.f*scale*s;
    }
    if (t < 1024) {
        int h = t >> 4, j = t & 15;
        int ky = (j < 8) ? j : j + 48;
        float s, c; sincosf(((ky*h)&63)*PI2_64, &s, &c);
        g_twF_[t] = make_float2(c, -s);
        g_twI_[t] = make_float2(c,  s);
    }
}

__device__ __forceinline__ float gelu_fast(float a) {
    float z = 1.5957691216057308f * (a + 0.044715f*a*a*a);
    float e;
    asm("ex2.approx.f32 %0, %1;" : "=f"(e) : "f"(-1.4426950408889634f*z));
    float r;
    asm("rcp.approx.f32 %0, %1;" : "=f"(r) : "f"(1.0f + e));
    return a * r;
}

// ---------------- fc0 + fused forward-z DFT ----------------
__global__ void k_fc0(const float* __restrict__ u, const float* __restrict__ w,
                      const float* __restrict__ bias) {
    __shared__ float  su[3][64];
    __shared__ float  sw[3*CW], sb[CW];
    __shared__ float  sxo[CW][65];
    __shared__ float2 twf[64][MD];
    int tid = threadIdx.x;  // 256
    int blk = blockIdx.x;   // BN*4096
    int b = blk >> 12, dh = blk & 4095;
    for (int t = tid; t < 512; t += 256) ((float2*)twf)[t] = g_twf_[t];
    if (tid < 3*CW) sw[tid] = w[tid];
    if (tid < CW)   sb[tid] = bias[tid];
    if (tid < 192) {
        int j = tid >> 6, ww = tid & 63;
        su[j][ww] = u[((size_t)(b*3+j) << 18) + dh*64 + ww];
    }
    __syncthreads();
    {
        int ww = tid & 63, o0 = (tid >> 6)*8;
#pragma unroll
        for (int oi = 0; oi < 8; oi++) {
            int o = o0 + oi;
            float acc = sb[o] + su[0][ww]*sw[o] + su[1][ww]*sw[CW+o] + su[2][ww]*sw[2*CW+o];
            sxo[o][ww] = acc;
            g_x0[((size_t)(b*CW+o) << 18) + dh*64 + ww] = acc;
        }
    }
    __syncthreads();
    {
        int o = tid >> 3, k = tid & 7;
        u64t zacc = 0ull;
#pragma unroll
        for (int ww = 0; ww < 64; ww++)
            fma2(zacc, dup2(sxo[o][ww]), *(const u64t*)&twf[ww][k]);
        float re, im; up2(zacc, re, im);
        g_a[((size_t)((b*CW+o)*4096 + dh))*MD + k] = make_float2(re, im);
    }
}

// ---------------- forward y: 64 -> 16 modes (per (b,c,d)) ----------------
__global__ void k_fy() {
    __shared__ float2 sa[64][MD];
    __shared__ float2 tw[64][M2];
    int tid = threadIdx.x;  // 128
    int bcd = blockIdx.x;   // 8192
    for (int t = tid; t < 512; t += 128)
        ((float4*)tw)[t] = ((const float4*)g_twF_)[t];
    const float2* src = g_a + (size_t)bcd*64*MD;
    for (int i = tid; i < 64*MD; i += 128) sa[i>>3][i&7] = src[i];
    __syncthreads();
    int j = tid >> 3, k = tid & 7;
    float re = 0.f, im = 0.f;
#pragma unroll
    for (int h = 0; h < 64; h++) {
        float2 a = sa[h][k], t = tw[h][j];
        re += a.x*t.x - a.y*t.y;
        im += a.x*t.y + a.y*t.x;
    }
    g_b[((size_t)bcd*M2 + j)*MD + k] = make_float2(re, im);
}

// ---------------- forward x: 64 -> 16 modes (per (b,c,k)) ----------------
__global__ void k_fx() {
    __shared__ float2 sa[64][M2];
    __shared__ float2 tw[64][M2];
    int tid = threadIdx.x;  // 256
    int bc = blockIdx.x >> 3, k = blockIdx.x & 7;  // 1024 blocks
    for (int t = tid; t < 512; t += 256)
        ((float4*)tw)[t] = ((const float4*)g_twF_)[t];
    const float2* src = g_b + (size_t)bc*64*M2*MD + k;
    for (int i = tid; i < 64*M2; i += 256) sa[i>>4][i&15] = src[(size_t)i*MD];
    __syncthreads();
    int i_ = tid >> 4, j = tid & 15;
    float re = 0.f, im = 0.f;
#pragma unroll
    for (int d = 0; d < 64; d++) {
        float2 a = sa[d][j], t = tw[d][i_];
        re += a.x*t.x - a.y*t.y;
        im += a.x*t.y + a.y*t.x;
    }
    g_ft[(((size_t)bc*M2 + i_)*M2 + j)*MD + k] = make_float2(re, im);
}

// ---------------- spectral channel mix: block per (b,i,j), c-split 8 ----------------
__global__ void k_spec(const float* __restrict__ spw, int layer) {
    __shared__ float2 sa[CW][MD];        // 2 KB
    __shared__ float  red[8][CW][M2];    // 16 KB
    int tid = threadIdx.x;   // 256
    int blk = blockIdx.x;    // 1024
    int b = blk >> 8, i = (blk >> 4) & 15, j = blk & 15;
    int corner = (i >= 8 ? 1 : 0) + (j >= 8 ? 2 : 0);
    int m1 = i & 7, m2 = j & 7;
    {
        int c = tid >> 3, k = tid & 7;
        sa[c][k] = g_ft[(((size_t)(b*CW+c)*M2 + i)*M2 + j)*MD + k];
    }
    __syncthreads();
    int o = tid & 31, cq = tid >> 5;   // cq 0..7
    const float* wbase = spw + ((size_t)(layer*4 + corner)*CW*CW*512
                               + (size_t)(m1*64 + m2*8)) * 2;
    float accr[MD], acci[MD];
#pragma unroll
    for (int k = 0; k < MD; k++) { accr[k] = 0.f; acci[k] = 0.f; }
#pragma unroll
    for (int c4 = 0; c4 < 4; c4++) {
        int c = cq*4 + c4;
        const float4* wv = (const float4*)(wbase + (size_t)(c*32 + o)*1024);
        float4 w0 = wv[0], w1 = wv[1], w2 = wv[2], w3 = wv[3];
        const float4* av = (const float4*)&sa[c][0];
        float4 a0 = av[0], a1 = av[1], a2 = av[2], a3 = av[3];
        accr[0] += a0.x*w0.x - a0.y*w0.y;  acci[0] += a0.x*w0.y + a0.y*w0.x;
        accr[1] += a0.z*w0.z - a0.w*w0.w;  acci[1] += a0.z*w0.w + a0.w*w0.z;
        accr[2] += a1.x*w1.x - a1.y*w1.y;  acci[2] += a1.x*w1.y + a1.y*w1.x;
        accr[3] += a1.z*w1.z - a1.w*w1.w;  acci[3] += a1.z*w1.w + a1.w*w1.z;
        accr[4] += a2.x*w2.x - a2.y*w2.y;  acci[4] += a2.x*w2.y + a2.y*w2.x;
        accr[5] += a2.z*w2.z - a2.w*w2.w;  acci[5] += a2.z*w2.w + a2.w*w2.z;
        accr[6] += a3.x*w3.x - a3.y*w3.y;  acci[6] += a3.x*w3.y + a3.y*w3.x;
        accr[7] += a3.z*w3.z - a3.w*w3.w;  acci[7] += a3.z*w3.w + a3.w*w3.z;
    }
#pragma unroll
    for (int k = 0; k < MD; k++) {
        red[cq][o][2*k]   = accr[k];
        red[cq][o][2*k+1] = acci[k];
    }
    __syncthreads();
    float* gs = (float*)g_sf;
#pragma unroll
    for (int r = 0; r < 2; r++) {
        int idx = r*256 + tid;          // 512 outputs
        int o2 = idx >> 4, v = idx & 15;
        float s = red[0][o2][v] + red[1][o2][v] + red[2][o2][v] + red[3][o2][v]
                + red[4][o2][v] + red[5][o2][v] + red[6][o2][v] + red[7][o2][v];
        gs[((((size_t)(b*CW+o2)*M2 + i)*M2 + j)*MD)*2 + v] = s;
    }
}

// ---------------- inverse x: 16 modes -> 64 (per (b,o,k)) ----------------
__global__ void k_ix() {
    __shared__ float2 sa[M2][M2];
    __shared__ float2 tw[64][M2];
    int tid = threadIdx.x;  // 256
    int bo = blockIdx.x >> 3, k = blockIdx.x & 7;  // 1024 blocks
    for (int t = tid; t < 512; t += 256)
        ((float4*)tw)[t] = ((const float4*)g_twI_)[t];
    const float2* src = g_sf + (size_t)bo*M2*M2*MD + k;
    for (int t = tid; t < M2*M2; t += 256) sa[t>>4][t&15] = src[(size_t)t*MD];
    __syncthreads();
    for (int t = tid; t < 64*M2; t += 256) {
        int d = t >> 4, j = t & 15;
        float re = 0.f, im = 0.f;
#pragma unroll
        for (int ii = 0; ii < M2; ii++) {
            float2 a = sa[ii][j], w = tw[d][ii];
            re += a.x*w.x - a.y*w.y;
            im += a.x*w.y + a.y*w.x;
        }
        g_b[(((size_t)bo*64 + d)*M2 + j)*MD + k] = make_float2(re, im);
    }
}

// ---------------- inverse y: 16 modes -> 64 (per (b,o,d)) ----------------
__global__ void k_iy() {
    __shared__ float2 sa[M2][MD];
    __shared__ float2 tw[64][M2];
    int tid = threadIdx.x;  // 128
    int bod = blockIdx.x;   // 8192
    for (int t = tid; t < 512; t += 128)
        ((float4*)tw)[t] = ((const float4*)g_twI_)[t];
    const float2* src = g_b + (size_t)bod*M2*MD;
    for (int t = tid; t < M2*MD; t += 128) sa[t>>3][t&7] = src[t];
    __syncthreads();
    for (int t = tid; t < 64*MD; t += 128) {
        int h = t >> 3, k = t & 7;
        float re = 0.f, im = 0.f;
#pragma unroll
        for (int j = 0; j < M2; j++) {
            float2 a = sa[j][k], w = tw[h][j];
            re += a.x*w.x - a.y*w.y;
            im += a.x*w.y + a.y*w.x;
        }
        g_a[((size_t)bod*64 + h)*MD + k] = make_float2(re, im);
    }
}

// ---------------- layer update: 2 z-lines per block, f32x2, fused fwd-z ----------------
__global__ void __launch_bounds__(256) k_layer(const float* __restrict__ wpw,
                        const float* __restrict__ bpw,
                        int layer, int do_gelu, int flip, int do_fz) {
    __shared__ float  su[CW][128];      // 16 KB: first x pairs [c][ww*2+q], then out [c][q*64+ww]
    __shared__ float  szr[2][MD][CW];   // 2 KB
    __shared__ float  szi[2][MD][CW];   // 2 KB
    __shared__ float  sw[CW][CW];       // 4 KB
    __shared__ float  sb[CW];
    __shared__ float  crt[MD][64], cit[MD][64]; // 4 KB
    __shared__ float2 twf[64][MD];      // 4 KB
    const float* __restrict__ xin  = flip ? g_x1 : g_x0;
    float* __restrict__       xout = flip ? g_x0 : g_x1;
    int tid = threadIdx.x;  // 256
    int blk = blockIdx.x;   // BN*2048
    int b = blk >> 11, dh0 = (blk & 2047)*2;
    for (int t = tid; t < 512; t += 256) {
        ((float*)crt)[t] = g_crt_[t];
        ((float*)cit)[t] = g_cit_[t];
        ((float2*)twf)[t] = g_twf_[t];
    }
    for (int t = tid; t < 1024; t += 256) ((float*)sw)[t] = wpw[layer*1024 + t];
    if (tid < CW) sb[tid] = bpw[layer*CW + tid];
    // x load with pair transpose: global row (c) = 128 floats [q*64+ww]
    for (int t = tid; t < CW*32; t += 256) {
        int c = t >> 5, r4 = t & 31;
        float4 v = *(const float4*)&xin[((size_t)(b*CW+c)*4096 + dh0)*64 + r4*4];
        int r = r4*4, q = r >> 6, w0 = r & 63;
        su[c][(w0+0)*2+q] = v.x; su[c][(w0+1)*2+q] = v.y;
        su[c][(w0+2)*2+q] = v.z; su[c][(w0+3)*2+q] = v.w;
    }
    // z modes load
    for (int t = tid; t < 512; t += 256) {
        int o = t >> 4, q = (t >> 3) & 1, k = t & 7;
        float2 z = g_a[((size_t)(b*CW+o)*4096 + dh0+q)*MD + k];
        szr[q][k][o] = z.x; szi[q][k][o] = z.y;
    }
    __syncthreads();
    int ww = tid & 63;
    int o0 = (tid >> 6) * 8;
    u64t acc[2][4];
#pragma unroll
    for (int p = 0; p < 4; p++) {
        u64t bv = *(const u64t*)&sb[o0+2*p];
        acc[0][p] = bv; acc[1][p] = bv;
    }
#pragma unroll
    for (int c = 0; c < CW; c++) {
        float2 xc = *(const float2*)&su[c][ww*2];
        u64t x0 = dup2(xc.x), x1 = dup2(xc.y);
        ulonglong2 w01 = *(const ulonglong2*)&sw[c][o0];
        ulonglong2 w23 = *(const ulonglong2*)&sw[c][o0+4];
        fma2(acc[0][0], x0, w01.x); fma2(acc[0][1], x0, w01.y);
        fma2(acc[0][2], x0, w23.x); fma2(acc[0][3], x0, w23.y);
        fma2(acc[1][0], x1, w01.x); fma2(acc[1][1], x1, w01.y);
        fma2(acc[1][2], x1, w23.x); fma2(acc[1][3], x1, w23.y);
    }
#pragma unroll
    for (int k = 0; k < MD; k++) {
        u64t cr = dup2(crt[k][ww]);
        u64t ci = dup2(cit[k][ww]);
#pragma unroll
        for (int p = 0; p < 4; p++) {
            u64t zr0 = *(const u64t*)&szr[0][k][o0+2*p];
            u64t zi0 = *(const u64t*)&szi[0][k][o0+2*p];
            u64t zr1 = *(const u64t*)&szr[1][k][o0+2*p];
            u64t zi1 = *(const u64t*)&szi[1][k][o0+2*p];
            fma2(acc[0][p], zr0, cr); fma2(acc[0][p], zi0, ci);
            fma2(acc[1][p], zr1, cr); fma2(acc[1][p], zi1, ci);
        }
    }
    __syncthreads();   // all reads of su (x pairs) done; reuse as output staging
#pragma unroll
    for (int q = 0; q < 2; q++) {
#pragma unroll
        for (int p = 0; p < 4; p++) {
            float v0, v1; up2(acc[q][p], v0, v1);
            if (do_gelu) { v0 = gelu_fast(v0); v1 = gelu_fast(v1); }
            su[o0+2*p  ][q*64+ww] = v0;
            su[o0+2*p+1][q*64+ww] = v1;
        }
    }
    __syncthreads();
    // cooperative global store of x_out (both z-lines)
    for (int t = tid; t < CW*32; t += 256) {
        int c = t >> 5, r4 = t & 31;
        *(float4*)&xout[((size_t)(b*CW+c)*4096 + dh0)*64 + r4*4]
            = *(const float4*)&su[c][r4*4];
    }
    if (do_fz) {
        int o = tid >> 3, k = tid & 7;
#pragma unroll
        for (int q = 0; q < 2; q++) {
            u64t zacc = 0ull;
#pragma unroll
            for (int w2 = 0; w2 < 64; w2++)
                fma2(zacc, dup2(su[o][q*64+w2]), *(const u64t*)&twf[w2][k]);
            float re, im; up2(zacc, re, im);
            g_a[((size_t)(b*CW+o)*4096 + dh0+q)*MD + k] = make_float2(re, im);
        }
    }
}

// ---------------- fused fc1 -> gelu -> fc2 head (f32x2, 2 pts/thread) ----------------
__global__ void __launch_bounds__(256) k_fc(const float* __restrict__ w1,
                     const float* __restrict__ b1, const float* __restrict__ w2,
                     const float* __restrict__ b2, float* __restrict__ tau) {
    __shared__ float2 sw1d[FCHN][CW];   // duplicated weights: 32 KB
    __shared__ float2 sw2d[FCHN][6];
    __shared__ float  sb1[FCHN];
    __shared__ float  sb2[6];
    int tid = threadIdx.x;
    for (int t = tid; t < FCHN*CW; t += 256) {
        int h = t >> 5, c = t & 31;
        float v = w1[c*FCHN + h];
        sw1d[h][c] = make_float2(v, v);
    }
    for (int t = tid; t < FCHN*6; t += 256) {
        float v = w2[t];
        sw2d[t/6][t%6] = make_float2(v, v);
    }
    if (tid < FCHN) sb1[tid] = b1[tid];
    if (tid < 6)    sb2[tid] = b2[tid];
    __syncthreads();
    int p0 = blockIdx.x*512 + tid*2;
    int b = p0 >> 18, s = p0 & (SP-1);
    u64t xa[CW];
#pragma unroll
    for (int c = 0; c < CW; c++)
        xa[c] = *(const u64t*)&g_x0[(((size_t)b*CW + c) << 18) + s];
    u64t tacc[6];
#pragma unroll
    for (int o = 0; o < 6; o++) tacc[o] = dup2(sb2[o]);
    for (int h = 0; h < FCHN; h++) {
        u64t a01 = dup2(sb1[h]);
        const ulonglong2* wd = (const ulonglong2*)&sw1d[h][0];
#pragma unroll
        for (int cp = 0; cp < 16; cp++) {
            ulonglong2 w = wd[cp];
            fma2(a01, xa[2*cp],   w.x);
            fma2(a01, xa[2*cp+1], w.y);
        }
        float a0, a1; up2(a01, a0, a1);
        u64t g01 = pk2(gelu_fast(a0), gelu_fast(a1));
#pragma unroll
        for (int o = 0; o < 6; o++)
            fma2(tacc[o], g01, *(const u64t*)&sw2d[h][o]);
    }
#pragma unroll
    for (int o = 0; o < 6; o++) {
        float ta, tb; up2(tacc[o], ta, tb);
        *(float2*)&tau[(((size_t)b*6 + o) << 18) + s] = make_float2(ta, tb);
    }
}

// ---------------- hard NS core + 0.001*tau[:, :3] ----------------
__global__ void k_hard(const float* __restrict__ u, const float* __restrict__ tau,
                       float* __restrict__ out) {
    int idx = blockIdx.x*blockDim.x + threadIdx.x;
    if (idx >= BN*SP) return;
    int b = idx >> 18, s = idx & (SP-1);
    int d = s >> 12, h = (s >> 6) & 63, w = s & 63;
    const float dx = 2.0f*3.14159265358979323846f/64.0f;
    const float inv2dx = 1.0f/(2.0f*dx);
    const float invdx2 = 1.0f/(dx*dx);
    int dp = (((d+1)&63)<<12) | (h<<6) | w;
    int dm = (((d+63)&63)<<12) | (h<<6) | w;
    int hp = (d<<12) | (((h+1)&63)<<6) | w;
    int hm = (d<<12) | (((h+63)&63)<<6) | w;
    int wp = (d<<12) | (h<<6) | ((w+1)&63);
    int wm = (d<<12) | (h<<6) | ((w+63)&63);
    const float* ub = u + ((size_t)b*3 << 18);
    float uc[3];
#pragma unroll
    for (int i = 0; i < 3; i++) uc[i] = ub[(i<<18) + s];
#pragma unroll
    for (int i = 0; i < 3; i++) {
        const float* ui = ub + (i<<18);
        float xp = ui[dp], xm = ui[dm];
        float yp = ui[hp], ym = ui[hm];
        float zp = ui[wp], zm = ui[wm];
        float conv = -( uc[0]*(xp-xm) + uc[1]*(yp-ym) + uc[2]*(zp-zm) )*inv2dx;
        float lap  = (xp+xm+yp+ym+zp+zm - 6.f*uc[i])*invdx2;
        out[((size_t)(b*3+i)<<18) + s] = conv + 0.000185f*lap
                                       + 0.001f*tau[((size_t)(b*6+i)<<18) + s];
    }
}

extern "C" void kernel_launch(void* const* d_in, const int* in_sizes, int n_in,
                              void* d_out, int out_size) {
    (void)in_sizes; (void)n_in; (void)out_size;
    const float* u      = (const float*)d_in[0];
    const float* fc0_w  = (const float*)d_in[1];
    const float* fc0_b  = (const float*)d_in[2];
    const float* spec_w = (const float*)d_in[3];
    const float* w_pw   = (const float*)d_in[4];
    const float* b_pw   = (const float*)d_in[5];
    const float* fc1_w  = (const float*)d_in[6];
    const float* fc1_b  = (const float*)d_in[7];
    const float* fc2_w  = (const float*)d_in[8];
    const float* fc2_b  = (const float*)d_in[9];
    float* out = (float*)d_out;
    float* tau = out + (size_t)BN*3*SP;   // du_dt first, then tau

    k_init<<<4, 256>>>();
    k_fc0<<<BN*RR*RR, 256>>>(u, fc0_w, fc0_b);   // writes g_x0 + g_a (fwd-z)
    for (int l = 0; l < NLY; l++) {
        int flip = l & 1;  // input buffer: 0 -> g_x0, 1 -> g_x1
        k_fy  <<<BN*CW*RR,   128>>>();
        k_fx  <<<BN*CW*MD,   256>>>();
        k_spec<<<BN*M2*M2,   256>>>(spec_w, l);
        k_ix  <<<BN*CW*MD,   256>>>();
        k_iy  <<<BN*CW*RR,   128>>>();
        k_layer<<<BN*RR*RR/2, 256>>>(w_pw, b_pw, l,
                                     (l < NLY-1) ? 1 : 0, flip,
                                     (l < NLY-1) ? 1 : 0);
    }
    // after 4 layers (0->x1, 1->x0, 2->x1, 3->x0) final activations are in g_x0
    k_fc  <<<BN*SP/512, 256>>>(fc1_w, fc1_b, fc2_w, fc2_b, tau);
    k_hard<<<(BN*SP + 255)/256, 256>>>(u, tau, out);
}